// round 17
// baseline (speedup 1.0000x reference)
#include <cuda_runtime.h>
#include <cuda_fp16.h>

#define NMAX 100000
#define EMAXN 1600000

// ---- scratch (device globals). 16B-aligned for float4/RED.128 ----
__device__ __align__(16) __half g_xwh[NMAX * 32];   // f16 rel-projection (edge1 gather payload)
__device__ __align__(16) float g_xroot[NMAX * 32];  // fp32 root-projection
__device__ __align__(16) float g_sum1[NMAX * 32];
__device__ __align__(16) float g_cnt[NMAX];
__device__ __align__(16) float g_hr[NMAX * 8];
__device__ __align__(16) float g_hroot[NMAX * 8];
__device__ __align__(16) float g_sum2[NMAX * 8];
__device__ __align__(16) int4  g_sdw[EMAXN];        // (src, dst, w-bits, 0)
__device__ int g_is64;

// ---- helpers ----
__device__ __forceinline__ void red_add4(float* p, float4 v) {
    asm volatile("red.global.add.v4.f32 [%0], {%1,%2,%3,%4};"
                 :: "l"(p), "f"(v.x), "f"(v.y), "f"(v.z), "f"(v.w) : "memory");
}
__device__ __forceinline__ float tf32r(float f) {
    float r;
    asm("cvt.rna.tf32.f32 %0, %1;" : "=f"(r) : "f"(f));
    return r;
}
__device__ __forceinline__ void mma_tf32(float* d, const unsigned* a, unsigned b0, unsigned b1) {
    asm volatile("mma.sync.aligned.m16n8k8.row.col.f32.tf32.tf32.f32 "
        "{%0,%1,%2,%3}, {%4,%5,%6,%7}, {%8,%9}, {%0,%1,%2,%3};"
        : "+f"(d[0]), "+f"(d[1]), "+f"(d[2]), "+f"(d[3])
        : "r"(a[0]), "r"(a[1]), "r"(a[2]), "r"(a[3]), "r"(b0), "r"(b1));
}

// ---- K0: zero g_cnt + sniff int64 vs int32 layout ----
__global__ void k_zc(const int* __restrict__ ei, int N) {
    if (blockIdx.x == 0 && threadIdx.x == 0) {
        int nz = 0;
        #pragma unroll 4
        for (int i = 1; i < 256; i += 2) nz |= ei[i];
        g_is64 = (nz == 0);
    }
    int i = blockIdx.x * blockDim.x + threadIdx.x;
    if (i < N) g_cnt[i] = 0.f;
}

// ---- unpack indices (packed int4 with weight) + degree count ----
__global__ void __launch_bounds__(256) k_unpack(const int* __restrict__ ei,
                                                const float* __restrict__ ew,
                                                int E, int N) {
    int e = blockIdx.x * 256 + threadIdx.x;
    if (e >= E) return;
    int s, d;
    if (g_is64) { s = ei[2 * e];  d = ei[2 * E + 2 * e]; }
    else        { s = ei[e];      d = ei[E + e]; }
    if (s < 0 || s >= N) s = 0;
    if (d < 0 || d >= N) d = 0;
    g_sdw[e] = make_int4(s, d, __float_as_int(ew[e]), 0);
    atomicAdd(&g_cnt[d], 1.0f);
}

// ---- K1: fused projection via mma.sync tf32 tensor cores ----
// 128 threads / 4 warps; tile 128 nodes x 64 cols; warp = 32 nodes x 64 cols.
// Ws [64][72] (pitch 72: B-frag conflict-free), Xs [128][68] (A-frag conflict-free).
#define WPITCH 72
#define XPITCH 68
__global__ void __launch_bounds__(128, 4) k_gemm1(
    const float* __restrict__ x,
    const float* __restrict__ Wrel,
    const float* __restrict__ Wroot,
    int N)
{
    extern __shared__ float sm[];
    float* Ws = sm;                  // [64 k][72]
    float* Xs = sm + 64 * WPITCH;    // [128 node][68]

    const int t    = threadIdx.x;
    const int warp = t >> 5;
    const int lane = t & 31;
    const int gid  = lane >> 2;      // 0..7
    const int tid4 = lane & 3;       // 0..3
    const int m0   = warp * 32;
    const int n0   = blockIdx.x * 128;

    float d[2][8][4];
    #pragma unroll
    for (int mt = 0; mt < 2; mt++)
        #pragma unroll
        for (int nt = 0; nt < 8; nt++)
            #pragma unroll
            for (int r = 0; r < 4; r++) d[mt][nt][r] = 0.f;

    for (int kc = 0; kc < 128; kc += 64) {
        // stage W (tf32-rounded)
        #pragma unroll
        for (int i = t; i < 4096; i += 128) {
            int kk = i >> 6, col = i & 63;
            float w = (col < 32) ? Wrel[(kc + kk) * 32 + col]
                                 : Wroot[(kc + kk) * 32 + (col - 32)];
            Ws[kk * WPITCH + col] = tf32r(w);
        }
        // stage X (tf32-rounded), coalesced float4 gmem reads
        #pragma unroll
        for (int j = 0; j < 16; j++) {
            int idx  = t + 128 * j;          // 0..2047 float4 slots
            int kq   = idx & 15;
            int node = idx >> 4;
            int gn   = n0 + node;
            float4 v = (gn < N) ? *(const float4*)&x[gn * 128 + kc + kq * 4]
                                : make_float4(0.f, 0.f, 0.f, 0.f);
            v.x = tf32r(v.x); v.y = tf32r(v.y); v.z = tf32r(v.z); v.w = tf32r(v.w);
            *(float4*)&Xs[node * XPITCH + kq * 4] = v;
        }
        __syncthreads();

        #pragma unroll
        for (int kt = 0; kt < 8; kt++) {
            int k0 = kt * 8;
            unsigned a[2][4];
            #pragma unroll
            for (int mt = 0; mt < 2; mt++) {
                const float* ap  = &Xs[(m0 + mt * 16 + gid) * XPITCH + k0 + tid4];
                const float* ap8 = ap + 8 * XPITCH;
                a[mt][0] = __float_as_uint(ap[0]);
                a[mt][1] = __float_as_uint(ap8[0]);
                a[mt][2] = __float_as_uint(ap[4]);
                a[mt][3] = __float_as_uint(ap8[4]);
            }
            #pragma unroll
            for (int nt = 0; nt < 8; nt++) {
                const float* bp = &Ws[(k0 + tid4) * WPITCH + nt * 8 + gid];
                unsigned b0 = __float_as_uint(bp[0]);
                unsigned b1 = __float_as_uint(bp[4 * WPITCH]);
                mma_tf32(d[0][nt], a[0], b0, b1);
                mma_tf32(d[1][nt], a[1], b0, b1);
            }
        }
        __syncthreads();
    }

    // epilogue: D rows = m0 + mt*16 + gid (+8), cols = nt*8 + tid4*2 (+1)
    #pragma unroll
    for (int mt = 0; mt < 2; mt++) {
        #pragma unroll
        for (int rr = 0; rr < 2; rr++) {
            int node = n0 + m0 + mt * 16 + gid + rr * 8;
            if (node < N) {
                #pragma unroll
                for (int nt = 0; nt < 4; nt++) {       // rel cols 0..31 -> f16
                    int c = nt * 8 + tid4 * 2;
                    __half2 h = __floats2half2_rn(d[mt][nt][rr * 2], d[mt][nt][rr * 2 + 1]);
                    *(__half2*)&g_xwh[node * 32 + c] = h;
                }
                #pragma unroll
                for (int nt = 4; nt < 8; nt++) {       // root cols 32..63 -> fp32
                    int c = (nt - 4) * 8 + tid4 * 2;
                    *(float2*)&g_xroot[node * 32 + c] =
                        make_float2(d[mt][nt][rr * 2], d[mt][nt][rr * 2 + 1]);
                }
            }
        }
    }

    // zero this block's slices of g_sum1 / g_sum2
    {
        int node = n0 + t;
        if (node < N) {
            float4 z = make_float4(0.f, 0.f, 0.f, 0.f);
            float4* s1 = (float4*)&g_sum1[node * 32];
            #pragma unroll
            for (int q = 0; q < 8; q++) s1[q] = z;
            float4* s2 = (float4*)&g_sum2[node * 8];
            s2[0] = z; s2[1] = z;
        }
    }
}

// ---- edge pass 1 (weighted): 8 threads/edge, 8B f16 gather + RED.128 ----
__global__ void __launch_bounds__(256) k_edge1(int E) {
    int t = blockIdx.x * 256 + threadIdx.x;
    int e = t >> 3, p = t & 7;
    if (e >= E) return;
    int4 sdw = g_sdw[e];
    float w = __int_as_float(sdw.z);
    uint2 hv = *(const uint2*)&g_xwh[sdw.x * 32 + p * 4];
    float2 f0 = __half22float2(*(__half2*)&hv.x);
    float2 f1 = __half22float2(*(__half2*)&hv.y);
    float4 v = make_float4(f0.x * w, f0.y * w, f1.x * w, f1.y * w);
    red_add4(&g_sum1[sdw.y * 32 + p * 4], v);
}

// ---- combine layer 1 + project layer 2 ----
__global__ void __launch_bounds__(256) k_comb1(
    const float* __restrict__ b1,
    const float* __restrict__ Wrel2,    // [32][5]
    const float* __restrict__ Wroot2,   // [32][5]
    int N)
{
    __shared__ float sW[352];
    int t = threadIdx.x;
    for (int i = t; i < 352; i += 256) {
        sW[i] = (i < 160) ? Wrel2[i]
              : (i < 320) ? Wroot2[i - 160]
                          : b1[i - 320];
    }
    __syncthreads();

    int node = blockIdx.x * 256 + t;
    if (node >= N) return;

    float inv = 1.0f / fmaxf(g_cnt[node], 1.0f);
    const float4* sp = (const float4*)&g_sum1[node * 32];
    const float4* rp = (const float4*)&g_xroot[node * 32];

    float h[32];
    #pragma unroll
    for (int q = 0; q < 8; q++) {
        float4 s4 = sp[q];
        float4 r4 = rp[q];
        h[4 * q + 0] = fmaxf(s4.x * inv + r4.x + sW[320 + 4 * q + 0], 0.f);
        h[4 * q + 1] = fmaxf(s4.y * inv + r4.y + sW[320 + 4 * q + 1], 0.f);
        h[4 * q + 2] = fmaxf(s4.z * inv + r4.z + sW[320 + 4 * q + 2], 0.f);
        h[4 * q + 3] = fmaxf(s4.w * inv + r4.w + sW[320 + 4 * q + 3], 0.f);
    }

    float hr[5] = {0.f, 0.f, 0.f, 0.f, 0.f};
    float ho[5] = {0.f, 0.f, 0.f, 0.f, 0.f};
    #pragma unroll
    for (int j = 0; j < 32; j++) {
        float hv = h[j];
        #pragma unroll
        for (int c = 0; c < 5; c++) {
            hr[c] += hv * sW[j * 5 + c];
            ho[c] += hv * sW[160 + j * 5 + c];
        }
    }
    *(float4*)&g_hr[node * 8 + 0]    = make_float4(hr[0], hr[1], hr[2], hr[3]);
    *(float4*)&g_hr[node * 8 + 4]    = make_float4(hr[4], 0.f, 0.f, 0.f);
    *(float4*)&g_hroot[node * 8 + 0] = make_float4(ho[0], ho[1], ho[2], ho[3]);
    *(float4*)&g_hroot[node * 8 + 4] = make_float4(ho[4], 0.f, 0.f, 0.f);
}

// ---- edge pass 2: 2 threads/edge, LDG.128 + RED.128 ----
__global__ void __launch_bounds__(256) k_edge2(int E) {
    int t = blockIdx.x * 256 + threadIdx.x;
    int e = t >> 1, p = t & 1;
    if (e >= E) return;
    int4 sdw = g_sdw[e];
    float4 v = *(const float4*)&g_hr[sdw.x * 8 + p * 4];
    red_add4(&g_sum2[sdw.y * 8 + p * 4], v);
}

// ---- combine layer 2 + log_softmax ----
__global__ void __launch_bounds__(256) k_final(
    const float* __restrict__ b2,
    float* __restrict__ out,
    int N)
{
    int node = blockIdx.x * 256 + threadIdx.x;
    if (node >= N) return;
    float inv = 1.0f / fmaxf(g_cnt[node], 1.0f);
    float v[5];
    #pragma unroll
    for (int c = 0; c < 5; c++)
        v[c] = g_sum2[node * 8 + c] * inv + g_hroot[node * 8 + c] + b2[c];

    float m = v[0];
    #pragma unroll
    for (int c = 1; c < 5; c++) m = fmaxf(m, v[c]);
    float sum = 0.f;
    #pragma unroll
    for (int c = 0; c < 5; c++) sum += expf(v[c] - m);
    float lse = m + logf(sum);
    #pragma unroll
    for (int c = 0; c < 5; c++) out[node * 5 + c] = v[c] - lse;
}

extern "C" void kernel_launch(void* const* d_in, const int* in_sizes, int n_in,
                              void* d_out, int out_size)
{
    const float* x      = (const float*)d_in[0];
    const int*   ei     = (const int*)d_in[1];
    const float* ew     = (const float*)d_in[2];
    const float* Wrel1  = (const float*)d_in[3];
    const float* Wroot1 = (const float*)d_in[4];
    const float* b1     = (const float*)d_in[5];
    const float* Wrel2  = (const float*)d_in[6];
    const float* Wroot2 = (const float*)d_in[7];
    const float* b2     = (const float*)d_in[8];
    float*       out    = (float*)d_out;

    int N = out_size / 5;
    int E = in_sizes[1] / 2;

    const int GEMM_SMEM = (64 * WPITCH + 128 * XPITCH) * 4;   // 53248 B
    cudaFuncSetAttribute(k_gemm1, cudaFuncAttributeMaxDynamicSharedMemorySize, GEMM_SMEM);

    static cudaStream_t s2 = nullptr;
    static cudaEvent_t evFork = nullptr, evJoin = nullptr;
    if (!s2) {
        cudaStreamCreateWithFlags(&s2, cudaStreamNonBlocking);
        cudaEventCreateWithFlags(&evFork, cudaEventDisableTiming);
        cudaEventCreateWithFlags(&evJoin, cudaEventDisableTiming);
    }

    // fork: {zc -> unpack} on s2, gemm1 on main stream, join before edge1
    cudaEventRecord(evFork, 0);
    cudaStreamWaitEvent(s2, evFork, 0);
    k_zc    <<<(N + 255) / 256, 256, 0, s2>>>(ei, N);
    k_unpack<<<(E + 255) / 256, 256, 0, s2>>>(ei, ew, E, N);
    cudaEventRecord(evJoin, s2);

    k_gemm1 <<<(N + 127) / 128, 128, GEMM_SMEM>>>(x, Wrel1, Wroot1, N);
    cudaStreamWaitEvent(0, evJoin, 0);

    k_edge1 <<<(E * 8 + 255) / 256, 256>>>(E);
    k_comb1 <<<(N + 255) / 256, 256>>>(b1, Wrel2, Wroot2, N);
    k_edge2 <<<(E * 2 + 255) / 256, 256>>>(E);
    k_final <<<(N + 255) / 256, 256>>>(b2, out, N);
}